// round 17
// baseline (speedup 1.0000x reference)
#include <cuda_runtime.h>
#include <cuda_fp16.h>
#include <cstdint>

#define T_SEQ 2048
#define HID   4096
#define QKV_N 6144
#define HD    128
#define NHEADS 32
#define ATTN_SCALE 0.08838834764831845f   // 128^-0.5

// GEMM: BM=BN=128, BK=32 (fp16). A tile 128x64B (8KB), B tile 32x256B (8KB,
// [K,N] layout, trans-ldmatrix). 6 stages, barrier per chunk-PAIR, 2 CTAs/SM.
// Epilogue (fused-rope mode) stages the fp32 C tile: 128x132 floats (67.6KB).
#define GT 8192
#define GSTG 16384
#define GEMM_SMEM (6 * GSTG)   // 98304 >= 67584 epilogue staging

// Attention v5: Q 256x128 fp16 (64KB) + 2-stage KV (Kh,Kl,Vh 48KB each).
// P lives entirely in registers (C-frag == A-frag identity).
#define AQH 0
#define AKV 65536
#define AKVS 49152
#define ATTN_SMEM (AKV + 2 * AKVS)   // 163840

extern __shared__ char dyn_smem[];

// ---------------------------------------------------------------------------
// Scratch (allocation-free rule: __device__ globals)
// ---------------------------------------------------------------------------
__device__ __align__(16) __half g_ah[(size_t)T_SEQ * HID];    // GEMM A (fp16)
__device__ __align__(16) __half g_wq16[(size_t)HID * QKV_N];  // Wqkv fp16 [K,N]
__device__ __align__(16) __half g_wo16[(size_t)HID * HID];    // Wo fp16 [K,N]
__device__ __align__(16) __half g_qh[(size_t)T_SEQ * HID];    // roped+scaled Q fp16
__device__ __align__(16) __half g_kh[(size_t)T_SEQ * 1024];   // roped K hi
__device__ __align__(16) __half g_kl[(size_t)T_SEQ * 1024];   // roped K lo
__device__ __align__(16) __half g_vh[(size_t)T_SEQ * 1024];   // V (fp16)
__device__ __align__(8) float2 g_rope[(size_t)T_SEQ * 64];    // cos/sin table

// ---------------------------------------------------------------------------
// helpers
// ---------------------------------------------------------------------------
__device__ __forceinline__ uint32_t smem_u32(const void* p) {
  uint32_t a;
  asm("{ .reg .u64 t; cvta.to.shared.u64 t, %1; cvt.u32.u64 %0, t; }"
      : "=r"(a) : "l"(p));
  return a;
}

__device__ __forceinline__ void cp16(uint32_t dst, const void* src) {
  asm volatile("cp.async.cg.shared.global [%0], [%1], 16;"
               :: "r"(dst), "l"(src) : "memory");
}

__device__ __forceinline__ void ldsm4(unsigned r[4], uint32_t addr) {
  asm volatile("ldmatrix.sync.aligned.m8n8.x4.shared.b16 {%0,%1,%2,%3}, [%4];"
               : "=r"(r[0]), "=r"(r[1]), "=r"(r[2]), "=r"(r[3]) : "r"(addr));
}

__device__ __forceinline__ void ldsm4t(unsigned r[4], uint32_t addr) {
  asm volatile("ldmatrix.sync.aligned.m8n8.x4.trans.shared.b16 {%0,%1,%2,%3}, [%4];"
               : "=r"(r[0]), "=r"(r[1]), "=r"(r[2]), "=r"(r[3]) : "r"(addr));
}

__device__ __forceinline__ void mma_f16(float d[4], const unsigned a[4],
                                        unsigned b0, unsigned b1) {
  asm volatile(
      "mma.sync.aligned.m16n8k16.row.col.f32.f16.f16.f32 "
      "{%0,%1,%2,%3}, {%4,%5,%6,%7}, {%8,%9}, {%0,%1,%2,%3};"
      : "+f"(d[0]), "+f"(d[1]), "+f"(d[2]), "+f"(d[3])
      : "r"(a[0]), "r"(a[1]), "r"(a[2]), "r"(a[3]), "r"(b0), "r"(b1));
}

__device__ __forceinline__ void split_store(__half* H, __half* L, size_t idx,
                                            float v) {
  __half h = __float2half_rn(v);
  H[idx] = h;
  L[idx] = __float2half_rn(v - __half2float(h));
}

__device__ __forceinline__ unsigned pack_h2(float a, float b) {
  __half2 h = __floats2half2_rn(a, b);
  return *reinterpret_cast<unsigned*>(&h);
}

// ---------------------------------------------------------------------------
// Single merged prep kernel: Wqkv conv | Wo conv | hidden conv | rope table
// ---------------------------------------------------------------------------
__global__ void prep_all(const float4* __restrict__ Wq, const float4* __restrict__ Wo,
                         const float4* __restrict__ H, const int* __restrict__ pos) {
  const size_t nq = (size_t)HID * QKV_N / 4;
  const size_t no = (size_t)HID * HID / 4;
  const size_t nh = (size_t)T_SEQ * HID / 4;
  size_t i = (size_t)blockIdx.x * 256 + threadIdx.x;

  if (i < nq) {
    float4 v = Wq[i];
    __half2 h0 = __floats2half2_rn(v.x, v.y), h1 = __floats2half2_rn(v.z, v.w);
    uint2 ho; ho.x = *(unsigned*)&h0; ho.y = *(unsigned*)&h1;
    reinterpret_cast<uint2*>(g_wq16)[i] = ho;
    return;
  }
  i -= nq;
  if (i < no) {
    float4 v = Wo[i];
    __half2 h0 = __floats2half2_rn(v.x, v.y), h1 = __floats2half2_rn(v.z, v.w);
    uint2 ho; ho.x = *(unsigned*)&h0; ho.y = *(unsigned*)&h1;
    reinterpret_cast<uint2*>(g_wo16)[i] = ho;
    return;
  }
  i -= no;
  if (i < nh) {
    float4 v = H[i];
    __half2 h0 = __floats2half2_rn(v.x, v.y), h1 = __floats2half2_rn(v.z, v.w);
    uint2 ho; ho.x = *(unsigned*)&h0; ho.y = *(unsigned*)&h1;
    reinterpret_cast<uint2*>(g_ah)[i] = ho;
    return;
  }
  i -= nh;
  if (i < (size_t)T_SEQ * 64) {
    int t = (int)(i >> 6), d = (int)(i & 63);
    float p = (float)pos[t];
    float inv = expf(-((float)d * (1.0f / 64.0f)) * 13.815510557964274f);
    float fr = p * inv;
    g_rope[i] = make_float2(cosf(fr), sinf(fr));
  }
}

// ---------------------------------------------------------------------------
// 1-term fp16 GEMM, B in native [K,N] layout (trans-ldmatrix fragments).
// 6-stage cp.async pipeline, ONE barrier per chunk pair, 2 CTAs/SM.
// MODE 0: plain fp32 C store (Wo). MODE 1: fused RoPE epilogue (QKV).
// ---------------------------------------------------------------------------
template <int MODE>
__global__ __launch_bounds__(256, 2) void gemm_h1t(
    const __half* __restrict__ pA, const __half* __restrict__ pB,
    float* __restrict__ C, int N, int K) {
  const uint32_t smb = smem_u32(dyn_smem);

  const int tid  = threadIdx.x;
  const int lane = tid & 31;
  const int warp = tid >> 5;
  const int wm = warp & 3;
  const int wn = warp >> 2;
  const int bm = blockIdx.y * 128;
  const int bn = blockIdx.x * 128;

  const __half* aP = pA + (size_t)bm * K;
  const __half* bP = pB + bn;

  const int crow = tid >> 1;
  const int cs0  = (tid & 1) << 1;
  const int csw  = (crow >> 1) & 3;
  const uint32_t cd0 = (uint32_t)(crow * 64 + ((cs0 ^ csw) << 4));
  const uint32_t cd1 = (uint32_t)(crow * 64 + (((cs0 + 1) ^ csw) << 4));
  const int cse = cs0 << 3;

  const int brow = tid >> 3;
  const int bs0  = (tid & 7) << 1;
  const int brx  = brow & 7;
  const uint32_t bd0 = (uint32_t)(brow * 256 + ((bs0 ^ brx) << 4));
  const uint32_t bd1 = (uint32_t)(brow * 256 + (((bs0 + 1) ^ brx) << 4));

  const int rowA = wm * 32 + (lane & 7) + ((lane >> 3) & 1) * 8;
  const int hcA  = (lane >> 4) & 1;
  const int swA  = (rowA >> 1) & 3;
  const uint32_t aofs = (uint32_t)(rowA * 64);
  const uint32_t xsa0 = (uint32_t)(((0 * 2 + hcA) ^ swA) << 4);
  const uint32_t xsa1 = (uint32_t)(((1 * 2 + hcA) ^ swA) << 4);

  const int subm = lane >> 3;
  const int rVb  = (lane & 7) + ((subm & 1) << 3);
  const int hsB  = subm >> 1;

  float acc[2][8][4];
#pragma unroll
  for (int i = 0; i < 2; i++)
#pragma unroll
    for (int j = 0; j < 8; j++)
#pragma unroll
      for (int r = 0; r < 4; r++) acc[i][j][r] = 0.f;

  const int NC = K >> 5;  // even for all our K

#define ISSUE(c, st)                                                          \
  do {                                                                        \
    uint32_t sb = smb + (uint32_t)(st) * GSTG;                                \
    size_t ga = (size_t)crow * K + ((c) << 5) + cse;                          \
    cp16(sb + cd0, aP + ga); cp16(sb + cd1, aP + ga + 8);                     \
    size_t gb = (size_t)(((c) << 5) + brow) * N + bs0 * 8;                    \
    cp16(sb + GT + bd0, bP + gb); cp16(sb + GT + bd1, bP + gb + 8);           \
    asm volatile("cp.async.commit_group;" ::: "memory");                      \
  } while (0)

#define CHUNK(st)                                                             \
  do {                                                                        \
    const uint32_t sb = smb + (uint32_t)(st) * GSTG;                          \
    const uint32_t ab = sb + aofs;                                            \
    const uint32_t bb = sb + GT;                                              \
    _Pragma("unroll")                                                         \
    for (int kst = 0; kst < 2; ++kst) {                                       \
      const uint32_t xa = kst ? xsa1 : xsa0;                                  \
      const int rv = kst * 16 + rVb;                                          \
      const uint32_t bro = bb + (uint32_t)rv * 256;                           \
      const int rxv = rv & 7;                                                 \
      unsigned af[2][4], bf[4][4];                                            \
      ldsm4(af[0], ab + xa);                                                  \
      ldsm4(af[1], ab + 1024 + xa);                                           \
      _Pragma("unroll")                                                       \
      for (int p = 0; p < 4; ++p) {                                           \
        const int seg = wn * 8 + p * 2 + hsB;                                 \
        ldsm4t(bf[p], bro + (uint32_t)((seg ^ rxv) << 4));                    \
      }                                                                       \
      _Pragma("unroll")                                                       \
      for (int p = 0; p < 4; ++p)                                             \
        _Pragma("unroll")                                                     \
        for (int mi = 0; mi < 2; ++mi)                                        \
          _Pragma("unroll")                                                   \
          for (int sub = 0; sub < 2; ++sub)                                   \
            mma_f16(acc[mi][p * 2 + sub], af[mi], bf[p][sub * 2],             \
                    bf[p][sub * 2 + 1]);                                      \
    }                                                                         \
  } while (0)

  ISSUE(0, 0);
  ISSUE(1, 1);
  ISSUE(2, 2);
  ISSUE(3, 3);

  int sc = 0, si = 4;
  for (int c = 0; c < NC; c += 2) {
    asm volatile("cp.async.wait_group 2;" ::: "memory");
    __syncthreads();
    if (c + 4 < NC) {
      ISSUE(c + 4, si); si = (si + 1 == 6) ? 0 : si + 1;
      ISSUE(c + 5, si); si = (si + 1 == 6) ? 0 : si + 1;
    } else {
      asm volatile("cp.async.commit_group;" ::: "memory");
      asm volatile("cp.async.commit_group;" ::: "memory");
    }
    CHUNK(sc); sc = (sc + 1 == 6) ? 0 : sc + 1;
    CHUNK(sc); sc = (sc + 1 == 6) ? 0 : sc + 1;
  }
#undef ISSUE
#undef CHUNK

  const int g  = lane >> 2;
  const int tg = lane & 3;

  if (MODE == 0) {
#pragma unroll
    for (int mi = 0; mi < 2; mi++) {
      int r0 = bm + wm * 32 + mi * 16 + g;
#pragma unroll
      for (int ni = 0; ni < 8; ni++) {
        int c = bn + wn * 64 + ni * 8 + tg * 2;
        C[(size_t)r0 * N + c]           = acc[mi][ni][0];
        C[(size_t)r0 * N + c + 1]       = acc[mi][ni][1];
        C[(size_t)(r0 + 8) * N + c]     = acc[mi][ni][2];
        C[(size_t)(r0 + 8) * N + c + 1] = acc[mi][ni][3];
      }
    }
    return;
  }

  // ---- MODE 1: fused RoPE epilogue ----
  asm volatile("cp.async.wait_group 0;" ::: "memory");
  __syncthreads();
  float* csm = reinterpret_cast<float*>(dyn_smem);  // pitch 132 floats
#pragma unroll
  for (int mi = 0; mi < 2; mi++) {
    int r0 = wm * 32 + mi * 16 + g;
#pragma unroll
    for (int ni = 0; ni < 8; ni++) {
      int cc = wn * 64 + ni * 8 + tg * 2;
      csm[r0 * 132 + cc]           = acc[mi][ni][0];
      csm[r0 * 132 + cc + 1]       = acc[mi][ni][1];
      csm[(r0 + 8) * 132 + cc]     = acc[mi][ni][2];
      csm[(r0 + 8) * 132 + cc + 1] = acc[mi][ni][3];
    }
  }
  __syncthreads();

  const int head = bn >> 7;
  if (head < 32) {
    for (int i = tid; i < 128 * 64; i += 256) {
      int r = i >> 6, d = i & 63;
      int t = bm + r;
      float2 rc = g_rope[(size_t)t * 64 + d];
      float x1 = csm[r * 132 + d], x2 = csm[r * 132 + d + 64];
      size_t o = (size_t)t * 4096 + head * 128 + d;
      g_qh[o]      = __float2half_rn((x1 * rc.x - x2 * rc.y) * ATTN_SCALE);
      g_qh[o + 64] = __float2half_rn((x2 * rc.x + x1 * rc.y) * ATTN_SCALE);
    }
  } else if (head < 40) {
    const int kh = head - 32;
    for (int i = tid; i < 128 * 64; i += 256) {
      int r = i >> 6, d = i & 63;
      int t = bm + r;
      float2 rc = g_rope[(size_t)t * 64 + d];
      float x1 = csm[r * 132 + d], x2 = csm[r * 132 + d + 64];
      size_t o = (size_t)t * 1024 + kh * 128 + d;
      split_store(g_kh, g_kl, o,      x1 * rc.x - x2 * rc.y);
      split_store(g_kh, g_kl, o + 64, x2 * rc.x + x1 * rc.y);
    }
  } else {
    const int vh = head - 40;
    for (int i = tid; i < 128 * 128; i += 256) {
      int r = i >> 7, d = i & 127;
      g_vh[(size_t)(bm + r) * 1024 + vh * 128 + d] =
          __float2half_rn(csm[r * 132 + d]);
    }
  }
}

// ---------------------------------------------------------------------------
// Flash attention v5: 256-row Q tiles, 512 threads / 16 warps, double-buffered
// KV, 2-term S, 1-term PV.  P stays in registers: S C-fragment == PV A-fragment
// (a0=rows g k-lo, a1=rows g+8 k-lo, a2/a3 = k-hi halves; ni=2*k2 maps cols).
// ---------------------------------------------------------------------------
__global__ __launch_bounds__(512) void attn5(__half* __restrict__ oh) {
  char* smc = dyn_smem;
  const uint32_t smb = smem_u32(smc);

  const int h = blockIdx.x;
  const int qt = (gridDim.y - 1) - blockIdx.y;   // heavy tiles first
  const int kvh = h >> 2;
  const int q0 = qt * 256;
  const int jmax = 4 * qt + 3;
  const int tid = threadIdx.x, lane = tid & 31, w = tid >> 5;
  const int g = lane >> 2, tg = lane & 3;

  // ---- Q tile load (once): 256 rows x 128 cols fp16 ----
  {
    const int row = tid >> 1, s0 = (tid & 1) * 8, rx = row & 7;
    const size_t gq = (size_t)(q0 + row) * 4096 + h * 128 + s0 * 8;
    const uint32_t dr = smb + row * 256;
#pragma unroll
    for (int s = 0; s < 8; ++s) {
      uint32_t d = dr + (((s0 + s) ^ rx) << 4);
      cp16(AQH + d, g_qh + gq + s * 8);
    }
    asm volatile("cp.async.commit_group;" ::: "memory");
  }

  // KV: 64 rows x 16 segs x 3 arrays; 512 threads -> 8/row, 2 segs each
  const int kvrow = tid >> 3, kvs0 = (tid & 7) * 2, kvrx = kvrow & 7;

#define KV_ISSUE(j, stg)                                                      \
  do {                                                                        \
    const uint32_t base = smb + AKV + (uint32_t)(stg) * AKVS;                 \
    const size_t gk = (size_t)((j) * 64 + kvrow) * 1024 + kvh * 128 + kvs0 * 8; \
    _Pragma("unroll")                                                         \
    for (int s = 0; s < 2; ++s) {                                             \
      uint32_t d = (uint32_t)(kvrow * 256 + (((kvs0 + s) ^ kvrx) << 4));      \
      cp16(base + d,         g_kh + gk + s * 8);                              \
      cp16(base + 16384 + d, g_kl + gk + s * 8);                              \
      cp16(base + 32768 + d, g_vh + gk + s * 8);                              \
    }                                                                         \
    asm volatile("cp.async.commit_group;" ::: "memory");                      \
  } while (0)

  KV_ISSUE(0, 0);

  const int rowA = w * 16 + (lane & 7) + ((lane >> 3) & 1) * 8;
  const int rxA = lane & 7;
  const int hcA = (lane >> 4) & 1;
  const uint32_t aQ = smb + (uint32_t)rowA * 256;
  const int rBb = (lane & 7) + ((lane >> 4) & 1) * 8;
  const int hcB = (lane >> 3) & 1;
  const int subm = lane >> 3;
  const int rV = (lane & 7) + ((subm & 1) << 3);
  const int hsV = subm >> 1;

  float m0 = -1e30f, m1 = -1e30f, l0 = 0.f, l1 = 0.f;
  float O[16][4];
#pragma unroll
  for (int i = 0; i < 16; i++)
#pragma unroll
    for (int r = 0; r < 4; r++) O[i][r] = 0.f;

  for (int j = 0; j <= jmax; ++j) {
    __syncthreads();
    if (j < jmax) {
      KV_ISSUE(j + 1, (j + 1) & 1);
      asm volatile("cp.async.wait_group 1;" ::: "memory");
    } else {
      asm volatile("cp.async.wait_group 0;" ::: "memory");
    }
    __syncthreads();

    const uint32_t kvb = smb + AKV + (uint32_t)(j & 1) * AKVS;

    // ---- S = Qs K^T, 2-term (Q fp16 x (Kh + Kl)) ----
    float s[8][4];
#pragma unroll
    for (int ni = 0; ni < 8; ni++)
#pragma unroll
      for (int r = 0; r < 4; r++) s[ni][r] = 0.f;

#pragma unroll
    for (int kst = 0; kst < 8; ++kst) {
      unsigned qh[4];
      const uint32_t xa = (uint32_t)(((kst * 2 + hcA) ^ rxA) << 4);
      ldsm4(qh, aQ + xa);
#pragma unroll
      for (int p = 0; p < 4; ++p) {
        const int rb = p * 16 + rBb;
        const uint32_t ab =
            kvb + (uint32_t)rb * 256 + (uint32_t)(((kst * 2 + hcB) ^ (rb & 7)) << 4);
        unsigned kh[4], kl[4];
        ldsm4(kh, ab);
        ldsm4(kl, ab + 16384);
        const int n0i = p * 2;
        mma_f16(s[n0i],     qh, kh[0], kh[1]);
        mma_f16(s[n0i + 1], qh, kh[2], kh[3]);
        mma_f16(s[n0i],     qh, kl[0], kl[1]);
        mma_f16(s[n0i + 1], qh, kl[2], kl[3]);
      }
    }

    // ---- online softmax ----
    const int gr0 = q0 + w * 16 + g;
    const int gr1 = gr0 + 8;
    float tm0 = -1e30f, tm1 = -1e30f;
#pragma unroll
    for (int ni = 0; ni < 8; ni++) {
#pragma unroll
      for (int cc = 0; cc < 2; cc++) {
        int gc = j * 64 + ni * 8 + tg * 2 + cc;
        float v0 = s[ni][cc];
        float v1 = s[ni][2 + cc];
        if (gc > gr0) v0 = -1e30f;
        if (gc > gr1) v1 = -1e30f;
        s[ni][cc] = v0;
        s[ni][2 + cc] = v1;
        tm0 = fmaxf(tm0, v0);
        tm1 = fmaxf(tm1, v1);
      }
    }
    tm0 = fmaxf(tm0, __shfl_xor_sync(0xffffffffu, tm0, 1));
    tm0 = fmaxf(tm0, __shfl_xor_sync(0xffffffffu, tm0, 2));
    tm1 = fmaxf(tm1, __shfl_xor_sync(0xffffffffu, tm1, 1));
    tm1 = fmaxf(tm1, __shfl_xor_sync(0xffffffffu, tm1, 2));

    float nm0 = fmaxf(m0, tm0), nm1 = fmaxf(m1, tm1);
    float a0 = __expf(m0 - nm0), a1 = __expf(m1 - nm1);

    // P packed directly into A-fragment registers
    unsigned pfa[8], pfb[8];
    float ps0 = 0.f, ps1 = 0.f;
#pragma unroll
    for (int ni = 0; ni < 8; ni++) {
      float p00 = __expf(s[ni][0] - nm0);
      float p01 = __expf(s[ni][1] - nm0);
      float p10 = __expf(s[ni][2] - nm1);
      float p11 = __expf(s[ni][3] - nm1);
      ps0 += p00 + p01;
      ps1 += p10 + p11;
      pfa[ni] = pack_h2(p00, p01);
      pfb[ni] = pack_h2(p10, p11);
    }
    ps0 += __shfl_xor_sync(0xffffffffu, ps0, 1);
    ps0 += __shfl_xor_sync(0xffffffffu, ps0, 2);
    ps1 += __shfl_xor_sync(0xffffffffu, ps1, 1);
    ps1 += __shfl_xor_sync(0xffffffffu, ps1, 2);

    l0 = l0 * a0 + ps0;
    l1 = l1 * a1 + ps1;
    m0 = nm0;
    m1 = nm1;
#pragma unroll
    for (int ni = 0; ni < 16; ni++) {
      O[ni][0] *= a0; O[ni][1] *= a0;
      O[ni][2] *= a1; O[ni][3] *= a1;
    }

    // ---- O += P V (single pass, V fp16, P from registers) ----
#pragma unroll
    for (int k2 = 0; k2 < 4; ++k2) {
      unsigned pf[4];
      pf[0] = pfa[k2 * 2];
      pf[1] = pfb[k2 * 2];
      pf[2] = pfa[k2 * 2 + 1];
      pf[3] = pfb[k2 * 2 + 1];
      const int rv = k2 * 16 + rV;
      const uint32_t vb = kvb + 32768 + (uint32_t)rv * 256;
      const int rxv = rv & 7;
      unsigned vf[8][4];
#pragma unroll
      for (int dg = 0; dg < 8; ++dg)
        ldsm4t(vf[dg], vb + (uint32_t)(((dg * 2 + hsV) ^ rxv) << 4));
#pragma unroll
      for (int dg = 0; dg < 8; ++dg) {
        mma_f16(O[dg * 2],     pf, vf[dg][0], vf[dg][1]);
        mma_f16(O[dg * 2 + 1], pf, vf[dg][2], vf[dg][3]);
      }
    }
  }
#undef KV_ISSUE

  // epilogue -> fp16 (feeds 1-term Wo GEMM)
  const float inv0 = 1.f / l0;
  const float inv1 = 1.f / l1;
  const int r0 = q0 + w * 16 + g;
#pragma unroll
  for (int ni = 0; ni < 16; ni++) {
    const int c = h * HD + ni * 8 + tg * 2;
    const size_t i0 = (size_t)r0 * HID + c;
    const size_t i1 = (size_t)(r0 + 8) * HID + c;
    *reinterpret_cast<__half2*>(oh + i0) =
        __floats2half2_rn(O[ni][0] * inv0, O[ni][1] * inv0);
    *reinterpret_cast<__half2*>(oh + i1) =
        __floats2half2_rn(O[ni][2] * inv1, O[ni][3] * inv1);
  }
}

// ---------------------------------------------------------------------------
// launch
// ---------------------------------------------------------------------------
extern "C" void kernel_launch(void* const* d_in, const int* in_sizes, int n_in,
                              void* d_out, int out_size) {
  (void)in_sizes; (void)n_in; (void)out_size;
  const int*   positions = (const int*)d_in[0];
  const float* hidden    = (const float*)d_in[1];
  const float* Wqkv      = (const float*)d_in[2];
  const float* Wo        = (const float*)d_in[3];
  float* out = (float*)d_out;

  __half *ah, *wq16, *wo16;
  cudaGetSymbolAddress((void**)&ah, g_ah);
  cudaGetSymbolAddress((void**)&wq16, g_wq16);
  cudaGetSymbolAddress((void**)&wo16, g_wo16);

  cudaFuncSetAttribute(gemm_h1t<0>, cudaFuncAttributeMaxDynamicSharedMemorySize,
                       GEMM_SMEM);
  cudaFuncSetAttribute(gemm_h1t<1>, cudaFuncAttributeMaxDynamicSharedMemorySize,
                       GEMM_SMEM);
  cudaFuncSetAttribute(attn5, cudaFuncAttributeMaxDynamicSharedMemorySize,
                       ATTN_SMEM);

  // 0) All prep in one launch (weight/activation converts + rope table)
  const size_t nprep = (size_t)HID * QKV_N / 4 + (size_t)HID * HID / 4 +
                       (size_t)T_SEQ * HID / 4 + (size_t)T_SEQ * 64;
  prep_all<<<(unsigned)((nprep + 255) / 256), 256>>>(
      (const float4*)Wqkv, (const float4*)Wo, (const float4*)hidden, positions);

  // 1) QKV projection with fused RoPE epilogue (writes g_qh/g_kh/g_kl/g_vh)
  gemm_h1t<1><<<dim3(QKV_N / 128, T_SEQ / 128), 256, GEMM_SMEM>>>(
      ah, wq16, nullptr, QKV_N, HID);
  // 2) Flash attention (writes fp16 into g_ah)
  attn5<<<dim3(NHEADS, T_SEQ / 256), 512, ATTN_SMEM>>>(ah);
  // 3) Output projection
  gemm_h1t<0><<<dim3(HID / 128, T_SEQ / 128), 256, GEMM_SMEM>>>(
      ah, wo16, out, HID, HID);
}